// round 15
// baseline (speedup 1.0000x reference)
#include <cuda_runtime.h>
#include <cuda.h>

// ModuleSoftsplat forward summation splatting, tiled-gather v7.
// image [4,64,512,512] f32, flow [4,2,512,512] f32 -> out [4,64,512,512] f32.
//
// v7 vs v6 (182us gather): (1) 512-thread CTAs, 2 cells/thread -> 32 warps/SM
// (was 16) for latency hiding; (2) per-cell bin lists sorted by source index
// (one-time 9-element sorting network) so that slot-i reads across a warp hit
// spatially correlated smem addresses -> bank-conflict degree ~3 -> ~1.
// TMA double-buffered staging (depth 2, 4 channels/pass) unchanged.

#define SS_B   4
#define SS_C   64
#define SS_H   512
#define SS_W   512
#define SS_HW  (SS_H * SS_W)
#define SS_CHW (SS_C * SS_HW)

#define TS     32
#define HALO   8
#define RW     (TS + 2 * HALO)        // 48
#define RN     (RW * RW)              // 2304
#define KCAP   9
#define NCELLS (TS * TS)              // 1024
#define NPASS  16
#define CPB    4
#define BUFB   (CPB * RN * 4)         // 36864
#define NTHR   512

#define OVF_CAP (4 * SS_B * SS_HW)

#define SM_MBAR_OFF 0
#define SM_CNT_OFF  128
#define SM_BIN_OFF  (SM_CNT_OFF + NCELLS * 4)
#define SM_IMG0_OFF (SM_BIN_OFF + NCELLS * KCAP * 4)
#define SM_IMG1_OFF (SM_IMG0_OFF + BUFB)
#define SMEM_BYTES  (SM_IMG1_OFF + BUFB)      // 114,816 -> 2 CTAs/SM

__device__ int   g_ovf_n;
__device__ int   g_ovf_cell[OVF_CAP];   // (b<<18) | (y<<9) | x
__device__ int   g_ovf_src [OVF_CAP];   // (b<<18) | spatial
__device__ float g_ovf_w   [OVF_CAP];

__device__ __forceinline__ void ovf_append(int cellp, int src, float w) {
    int slot = atomicAdd(&g_ovf_n, 1);
    if (slot < OVF_CAP) {
        g_ovf_cell[slot] = cellp;
        g_ovf_src [slot] = src;
        g_ovf_w   [slot] = w;
    }
}

__global__ void ss_reset_kernel() { g_ovf_n = 0; }

__device__ __forceinline__ unsigned pack_entry(float w, int sidx) {
    unsigned b = __float_as_uint(w);
    b = (b + 0x800u) & 0xFFFFF000u;     // round weight bits to 20 high bits
    return b | (unsigned)sidx;          // low 12 bits = smem index (<2304)
}

__device__ __forceinline__ unsigned smem_u32(const void* p) {
    unsigned a;
    asm("{ .reg .u64 t; cvta.to.shared.u64 t, %1; cvt.u32.u64 %0, t; }"
        : "=r"(a) : "l"(p));
    return a;
}
__device__ __forceinline__ void mbar_init(unsigned addr, unsigned count) {
    asm volatile("mbarrier.init.shared.b64 [%0], %1;" :: "r"(addr), "r"(count) : "memory");
}
__device__ __forceinline__ void mbar_expect_tx(unsigned addr, unsigned bytes) {
    asm volatile("mbarrier.arrive.expect_tx.shared.b64 _, [%0], %1;"
                 :: "r"(addr), "r"(bytes) : "memory");
}
__device__ __forceinline__ void mbar_wait(unsigned addr, unsigned parity) {
    asm volatile(
        "{\n\t.reg .pred P;\n"
        "WLP%=:\n\t"
        "mbarrier.try_wait.parity.acquire.cta.shared::cta.b64 P, [%0], %1, 0x989680;\n\t"
        "@P bra WDN%=;\n\t"
        "bra WLP%=;\n"
        "WDN%=:\n\t}"
        :: "r"(addr), "r"(parity) : "memory");
}
__device__ __forceinline__ void tma_load3d(unsigned dst, const CUtensorMap* m,
                                           int x, int y, int z, unsigned mbar) {
    asm volatile(
        "cp.async.bulk.tensor.3d.shared::cta.global.tile.mbarrier::complete_tx::bytes "
        "[%0], [%1, {%2, %3, %4}], [%5];"
        :: "r"(dst), "l"(m), "r"(x), "r"(y), "r"(z), "r"(mbar) : "memory");
}

// 9-element sorting network (25 comparators), key = low 12 bits (source idx).
__device__ __forceinline__ void sort9(unsigned* a) {
#define CE(i, j) { unsigned x = a[i], y = a[j];                        \
                   if ((x & 0xFFFu) > (y & 0xFFFu)) { a[i] = y; a[j] = x; } }
    CE(0,3) CE(1,7) CE(2,5) CE(4,8)
    CE(0,7) CE(2,4) CE(3,8) CE(5,6)
    CE(0,2) CE(1,3) CE(4,5) CE(7,8)
    CE(1,4) CE(3,6) CE(5,7)
    CE(0,1) CE(2,4) CE(3,5) CE(6,8)
    CE(2,3) CE(4,5) CE(6,7)
    CE(1,2) CE(3,4) CE(5,6)
#undef CE
}

// ---------------------------------------------------------------------------
// Main tiled gather kernel. Grid: 1024 = b(2) | ty(4) | tx(4). 512 threads.
// ---------------------------------------------------------------------------
__global__ __launch_bounds__(NTHR, 2) void ss_gather_kernel(
    const __grid_constant__ CUtensorMap tmap,
    const float* __restrict__ img,
    const float* __restrict__ flow,
    float* __restrict__ out,
    int use_tma)
{
    extern __shared__ unsigned char sraw[];
    int*      s_cnt = (int*)(sraw + SM_CNT_OFF);
    unsigned* s_bin = (unsigned*)(sraw + SM_BIN_OFF);
    float*    s_buf[2] = { (float*)(sraw + SM_IMG0_OFF), (float*)(sraw + SM_IMG1_OFF) };

    const int tid = threadIdx.x;
    const int bi  = blockIdx.x;
    const int tx0 = (bi & 15) * TS;
    const int ty0 = ((bi >> 4) & 15) * TS;
    const int b   = bi >> 8;

    const unsigned mbar0 = smem_u32(sraw + SM_MBAR_OFF);
    const unsigned mbar1 = mbar0 + 8;
    const unsigned buf0u = smem_u32(sraw + SM_IMG0_OFF);
    const unsigned buf1u = smem_u32(sraw + SM_IMG1_OFF);

    if (use_tma && tid == 0) {
        mbar_init(mbar0, 1);
        mbar_init(mbar1, 1);
        asm volatile("fence.proxy.async.shared::cta;" ::: "memory");
        mbar_expect_tx(mbar0, BUFB);
        #pragma unroll
        for (int j = 0; j < CPB; j++)
            tma_load3d(buf0u + j * (RN * 4), &tmap,
                       tx0 - HALO, ty0 - HALO, b * SS_C + j, mbar0);
        mbar_expect_tx(mbar1, BUFB);
        #pragma unroll
        for (int j = 0; j < CPB; j++)
            tma_load3d(buf1u + j * (RN * 4), &tmap,
                       tx0 - HALO, ty0 - HALO, b * SS_C + CPB + j, mbar1);
    }

    for (int i = tid; i < NCELLS; i += NTHR) s_cnt[i] = 0;
    __syncthreads();

    // -------- Phase A: bin contributors (channel-independent, once) --------
    const float* flowb = flow + (size_t)b * 2 * SS_HW;
    #pragma unroll
    for (int it = 0; it < (RN + NTHR - 1) / NTHR; it++) {
        int i = tid + it * NTHR;
        if (i >= RN) break;
        int ly = i / RW, lx = i - ly * RW;
        int gy = ty0 - HALO + ly, gx = tx0 - HALO + lx;
        if ((unsigned)gx >= SS_W || (unsigned)gy >= SS_H) continue;
        int sp = (gy << 9) + gx;
        float fx = flowb[sp]         + (float)gx;
        float fy = flowb[sp + SS_HW] + (float)gy;
        float x0f = floorf(fx), y0f = floorf(fy);
        int x0 = (int)x0f, y0 = (int)y0f;
        float wx1 = fx - x0f, wx0 = 1.0f - wx1;
        float wy1 = fy - y0f, wy0 = 1.0f - wy1;
        int sidx = ly * RW + lx;
        bool own = (gx >= tx0) && (gx < tx0 + TS) && (gy >= ty0) && (gy < ty0 + TS);
        #pragma unroll
        for (int k = 0; k < 4; k++) {
            int dx = k & 1, dy = k >> 1;
            int cx = x0 + dx, cy = y0 + dy;
            if ((unsigned)cx >= SS_W || (unsigned)cy >= SS_H) continue;
            float w = (dx ? wx1 : wx0) * (dy ? wy1 : wy0);
            int lcx = cx - tx0, lcy = cy - ty0;
            if ((unsigned)lcx < TS && (unsigned)lcy < TS) {
                int cid  = (lcy << 5) + lcx;
                int slot = atomicAdd(&s_cnt[cid], 1);
                if (slot < KCAP)
                    s_bin[cid * KCAP + slot] = pack_entry(w, sidx);
                else
                    ovf_append((b << 18) | (cy << 9) | cx, (b << 18) | sp, w);
            } else if (own) {
                int tcx = cx & ~(TS - 1), tcy = cy & ~(TS - 1);
                bool cap = (gx >= tcx - HALO) && (gx < tcx + TS + HALO) &&
                           (gy >= tcy - HALO) && (gy < tcy + TS + HALO);
                if (!cap)
                    ovf_append((b << 18) | (cy << 9) | cx, (b << 18) | sp, w);
            }
        }
    }
    __syncthreads();

    // Each thread owns 2 cells: tid and tid+512.
    const int n0 = min(s_cnt[tid       ], KCAP);
    const int n1 = min(s_cnt[tid + NTHR], KCAP);
    const int nmax = max(n0, n1);

    unsigned* bp0 = s_bin + (tid       ) * KCAP;
    unsigned* bp1 = s_bin + (tid + NTHR) * KCAP;

    // Sort both bin lists by source index (thread-local; bins for these cells
    // were written by other threads, already fenced by the barrier above).
    {
        unsigned t[KCAP];
        #pragma unroll
        for (int i = 0; i < KCAP; i++) t[i] = (i < n0) ? bp0[i] : 0xFFFFFFFFu;
        sort9(t);
        #pragma unroll
        for (int i = 0; i < KCAP; i++) if (i < n0) bp0[i] = t[i];
        #pragma unroll
        for (int i = 0; i < KCAP; i++) t[i] = (i < n1) ? bp1[i] : 0xFFFFFFFFu;
        sort9(t);
        #pragma unroll
        for (int i = 0; i < KCAP; i++) if (i < n1) bp1[i] = t[i];
    }

    const int g0 = ((ty0 + (tid >> 5)) << 9) + tx0 + (tid & 31);   // rows 0..15
    const int g1 = g0 + 16 * SS_W;                                 // rows 16..31

    float* outb = out + (size_t)b * SS_CHW;

    // -------- Phase B: 16 passes of 4 channels, double-buffered --------
    for (int p = 0; p < NPASS; p++) {
        const int s = p & 1;
        const float* sb = s_buf[s];

        if (use_tma) {
            mbar_wait(s ? mbar1 : mbar0, (p >> 1) & 1);
        } else {
            const float* ic = img + (size_t)b * SS_CHW + (size_t)(p * CPB) * SS_HW;
            float* wbuf = s_buf[s];
            #pragma unroll
            for (int it = 0; it < (RN + NTHR - 1) / NTHR; it++) {
                int i = tid + it * NTHR;
                if (i >= RN) break;
                int ly = i / RW, lx = i - ly * RW;
                int gy = ty0 - HALO + ly, gx = tx0 - HALO + lx;
                float v0 = 0.f, v1 = 0.f, v2 = 0.f, v3 = 0.f;
                if ((unsigned)gx < SS_W && (unsigned)gy < SS_H) {
                    int g = (gy << 9) + gx;
                    v0 = ic[g];
                    v1 = ic[g + 1 * SS_HW];
                    v2 = ic[g + 2 * SS_HW];
                    v3 = ic[g + 3 * SS_HW];
                }
                wbuf[i] = v0;
                wbuf[i + RN] = v1;
                wbuf[i + 2 * RN] = v2;
                wbuf[i + 3 * RN] = v3;
            }
            __syncthreads();
        }

        float4 A0 = make_float4(0.f, 0.f, 0.f, 0.f);
        float4 A1 = A0;

        for (int i = 0; i < nmax; i++) {
            if (i < n0) {
                unsigned e = bp0[i];
                float w = __uint_as_float(e & 0xFFFFF000u);
                const float* q = sb + (e & 0xFFFu);
                A0.x += w * q[0];      A0.y += w * q[RN];
                A0.z += w * q[2 * RN]; A0.w += w * q[3 * RN];
            }
            if (i < n1) {
                unsigned e = bp1[i];
                float w = __uint_as_float(e & 0xFFFFF000u);
                const float* q = sb + (e & 0xFFFu);
                A1.x += w * q[0];      A1.y += w * q[RN];
                A1.z += w * q[2 * RN]; A1.w += w * q[3 * RN];
            }
        }

        float* o = outb + (size_t)(p * CPB) * SS_HW;
        __stcs(o + g0, A0.x); __stcs(o + SS_HW + g0, A0.y);
        __stcs(o + 2 * SS_HW + g0, A0.z); __stcs(o + 3 * SS_HW + g0, A0.w);
        __stcs(o + g1, A1.x); __stcs(o + SS_HW + g1, A1.y);
        __stcs(o + 2 * SS_HW + g1, A1.z); __stcs(o + 3 * SS_HW + g1, A1.w);

        __syncthreads();   // all reads of buf[s] complete before refill

        if (use_tma && p + 2 < NPASS && tid == 0) {
            unsigned mb = s ? mbar1 : mbar0;
            unsigned bu = s ? buf1u : buf0u;
            mbar_expect_tx(mb, BUFB);
            #pragma unroll
            for (int j = 0; j < CPB; j++)
                tma_load3d(bu + j * (RN * 4), &tmap,
                           tx0 - HALO, ty0 - HALO,
                           b * SS_C + (p + 2) * CPB + j, mb);
        }
    }
}

// ---------------------------------------------------------------------------
// Overflow splat: rare contributions, global atomics, all 64 channels.
// ---------------------------------------------------------------------------
__global__ __launch_bounds__(256) void ss_ovf_kernel(
    const float* __restrict__ img, float* __restrict__ out)
{
    int n = g_ovf_n;
    if (n > OVF_CAP) n = OVF_CAP;
    long long total = (long long)n * SS_C;
    long long stride = (long long)gridDim.x * blockDim.x;
    for (long long i = blockIdx.x * (long long)blockDim.x + threadIdx.x;
         i < total; i += stride) {
        int e  = (int)(i >> 6);
        int c  = (int)(i & 63);
        int cellp = g_ovf_cell[e];
        int bb    = (cellp >> 18) & 3;
        int sp    = cellp & (SS_HW - 1);
        int ssp   = g_ovf_src[e] & (SS_HW - 1);
        size_t plane = (size_t)bb * SS_CHW + (size_t)c * SS_HW;
        atomicAdd(out + plane + sp, img[plane + ssp] * g_ovf_w[e]);
    }
}

// ---------------------------------------------------------------------------
typedef CUresult (*EncodeTiledFn)(
    CUtensorMap*, CUtensorMapDataType, cuuint32_t, void*,
    const cuuint64_t*, const cuuint64_t*, const cuuint32_t*, const cuuint32_t*,
    CUtensorMapInterleave, CUtensorMapSwizzle, CUtensorMapL2promotion,
    CUtensorMapFloatOOBfill);

extern "C" void kernel_launch(void* const* d_in, const int* in_sizes, int n_in,
                              void* d_out, int out_size) {
    const float* img  = (const float*)d_in[0];
    const float* flow = (const float*)d_in[1];
    float* out = (float*)d_out;

    CUtensorMap tmap;
    memset(&tmap, 0, sizeof(tmap));
    int use_tma = 0;
    void* fp = nullptr;
    cudaDriverEntryPointQueryResult qres = cudaDriverEntryPointSymbolNotFound;
#if CUDART_VERSION >= 12050
    cudaGetDriverEntryPointByVersion("cuTensorMapEncodeTiled", &fp, 12000,
                                     cudaEnableDefault, &qres);
#else
    cudaGetDriverEntryPoint("cuTensorMapEncodeTiled", &fp,
                            cudaEnableDefault, &qres);
#endif
    if (fp && qres == cudaDriverEntryPointSuccess) {
        cuuint64_t dims[3]    = { SS_W, SS_H, SS_B * SS_C };
        cuuint64_t strides[2] = { SS_W * 4ull, (cuuint64_t)SS_HW * 4ull };
        cuuint32_t box[3]     = { RW, RW, 1 };
        cuuint32_t estr[3]    = { 1, 1, 1 };
        CUresult r = ((EncodeTiledFn)fp)(
            &tmap, CU_TENSOR_MAP_DATA_TYPE_FLOAT32, 3, (void*)img,
            dims, strides, box, estr,
            CU_TENSOR_MAP_INTERLEAVE_NONE, CU_TENSOR_MAP_SWIZZLE_NONE,
            CU_TENSOR_MAP_L2_PROMOTION_L2_128B,
            CU_TENSOR_MAP_FLOAT_OOB_FILL_NONE);
        if (r == CUDA_SUCCESS) use_tma = 1;
    }

    cudaFuncSetAttribute(ss_gather_kernel,
                         cudaFuncAttributeMaxDynamicSharedMemorySize, SMEM_BYTES);

    ss_gather_kernel<<<SS_B * 16 * 16, NTHR, SMEM_BYTES>>>(tmap, img, flow, out, use_tma);
    ss_ovf_kernel<<<512, 256>>>(img, out);
    ss_reset_kernel<<<1, 1>>>();
}